// round 2
// baseline (speedup 1.0000x reference)
#include <cuda_runtime.h>
#include <cuda_bf16.h>
#include <cstddef>

// Problem constants
#define EMB   768
#define DK    256
#define DV    256
#define BB    8
#define NN    2048
#define HH    3
#define MALL  (BB*NN)          // 16384

// Scratch (device globals — no allocation allowed)
__device__ float g_Q[HH * MALL * DK];             // [h][b*N+n][d]
__device__ float g_K[HH * MALL * DK];
__device__ float g_V[HH * MALL * DV];
__device__ float g_S[(size_t)HH * BB * NN * NN];  // [h*8+b][n][m]  (402 MB)
__device__ float g_C[MALL * (HH * DV)];           // concat [b*N+n][h*256+d]

// ---------------------------------------------------------------------------
// f32x2 packed helpers (B300 FFMA2: 2 FMAs per issue; ptxas never auto-fuses)
// ---------------------------------------------------------------------------
__device__ __forceinline__ unsigned long long pack2(float x) {
    unsigned long long r;
    asm("mov.b64 %0, {%1, %1};" : "=l"(r) : "f"(x));
    return r;
}
__device__ __forceinline__ void fma2(unsigned long long& d,
                                     unsigned long long a,
                                     unsigned long long b) {
    asm("fma.rn.f32x2 %0, %1, %2, %0;" : "+l"(d) : "l"(a), "l"(b));
}
__device__ __forceinline__ float lo32(unsigned long long v) {
    return __uint_as_float((unsigned int)v);
}
__device__ __forceinline__ float hi32(unsigned long long v) {
    return __uint_as_float((unsigned int)(v >> 32));
}

// ---------------------------------------------------------------------------
// Generic batched SGEMM: C = alpha * A * op(B) (+ bias)
//   BM=BN=128, BK=16, 256 threads, 8x8 microtile, FFMA2 accumulation.
//   TRANSB=false: C[i,j] = sum_k A[i,k] * B[k,j]   (B is K x Ncol, ldb)
//   TRANSB=true : C[i,j] = sum_k A[i,k] * B[j,k]   (B is Ncol x K, ldb)
//   Batch: z = blockIdx.z; z1 = z / Z2, z2 = z % Z2; base += z1*s?1 + z2*s?2.
//   All dims assumed multiples of the tile (true for every launch here).
// ---------------------------------------------------------------------------
template<bool TRANSB, bool HASBIAS>
__global__ __launch_bounds__(256, 2)
void sgemm128(const float* __restrict__ A, int lda, long long sA1, long long sA2,
              const float* __restrict__ Bm, int ldb, long long sB1, long long sB2,
              const float* __restrict__ bias, long long sb1, long long sb2,
              float* __restrict__ Cm, int ldc, long long sC1, long long sC2,
              int Kdim, float alpha, int Z2)
{
    const int z  = blockIdx.z;
    const int z1 = z / Z2;
    const int z2 = z - z1 * Z2;
    A  += z1 * sA1 + z2 * sA2;
    Bm += z1 * sB1 + z2 * sB2;
    Cm += z1 * sC1 + z2 * sC2;
    if (HASBIAS) bias += z1 * sb1 + z2 * sb2;

    const int m0 = blockIdx.y * 128;
    const int n0 = blockIdx.x * 128;

    __shared__ float As[16][132];   // [k][m], padded: conflict-free scatter stores
    __shared__ float Bs[16][132];   // [k][n]

    const int tid = threadIdx.x;
    const int tx  = tid & 15;       // 0..15 -> 8 columns each
    const int ty  = tid >> 4;       // 0..15 -> 8 rows each

    unsigned long long acc[8][4];
#pragma unroll
    for (int i = 0; i < 8; i++)
#pragma unroll
        for (int j = 0; j < 4; j++) acc[i][j] = 0ull;

    for (int k0 = 0; k0 < Kdim; k0 += 16) {
        // ---- load A tile (transpose into As[k][m]) : 512 float4, 2/thread ----
#pragma unroll
        for (int t = 0; t < 2; t++) {
            const int f   = tid + t * 256;
            const int row = f >> 2;
            const int kq  = (f & 3) << 2;
            const float4 v = *(const float4*)(A + (size_t)(m0 + row) * lda + k0 + kq);
            As[kq + 0][row] = v.x;
            As[kq + 1][row] = v.y;
            As[kq + 2][row] = v.z;
            As[kq + 3][row] = v.w;
        }
        // ---- load B tile ----
        if (!TRANSB) {
#pragma unroll
            for (int t = 0; t < 2; t++) {
                const int f  = tid + t * 256;
                const int k  = f >> 5;
                const int nq = (f & 31) << 2;
                const float4 v = *(const float4*)(Bm + (size_t)(k0 + k) * ldb + n0 + nq);
                *(float4*)&Bs[k][nq] = v;
            }
        } else {
#pragma unroll
            for (int t = 0; t < 2; t++) {
                const int f   = tid + t * 256;
                const int row = f >> 2;      // n within tile
                const int kq  = (f & 3) << 2;
                const float4 v = *(const float4*)(Bm + (size_t)(n0 + row) * ldb + k0 + kq);
                Bs[kq + 0][row] = v.x;
                Bs[kq + 1][row] = v.y;
                Bs[kq + 2][row] = v.z;
                Bs[kq + 3][row] = v.w;
            }
        }
        __syncthreads();

        // ---- compute ----
#pragma unroll
        for (int kk = 0; kk < 16; kk++) {
            const float4 a0 = *(const float4*)&As[kk][ty * 8];
            const float4 a1 = *(const float4*)&As[kk][ty * 8 + 4];
            const longlong2 L0 = *(const longlong2*)&Bs[kk][tx * 8];
            const longlong2 L1 = *(const longlong2*)&Bs[kk][tx * 8 + 4];
            const unsigned long long b0 = (unsigned long long)L0.x;
            const unsigned long long b1 = (unsigned long long)L0.y;
            const unsigned long long b2 = (unsigned long long)L1.x;
            const unsigned long long b3 = (unsigned long long)L1.y;
            const float av[8] = {a0.x, a0.y, a0.z, a0.w, a1.x, a1.y, a1.z, a1.w};
#pragma unroll
            for (int i = 0; i < 8; i++) {
                const unsigned long long ap = pack2(av[i]);
                fma2(acc[i][0], ap, b0);
                fma2(acc[i][1], ap, b1);
                fma2(acc[i][2], ap, b2);
                fma2(acc[i][3], ap, b3);
            }
        }
        __syncthreads();
    }

    // ---- epilogue ----
    float bv[8];
    if (HASBIAS) {
#pragma unroll
        for (int j = 0; j < 8; j++) bv[j] = __ldg(bias + n0 + tx * 8 + j);
    }
#pragma unroll
    for (int i = 0; i < 8; i++) {
        float o[8];
#pragma unroll
        for (int j = 0; j < 4; j++) {
            o[2 * j]     = lo32(acc[i][j]) * alpha;
            o[2 * j + 1] = hi32(acc[i][j]) * alpha;
        }
        if (HASBIAS) {
#pragma unroll
            for (int j = 0; j < 8; j++) o[j] += bv[j];
        }
        float* dst = Cm + (size_t)(m0 + ty * 8 + i) * ldc + n0 + tx * 8;
        *(float4*)(dst)     = make_float4(o[0], o[1], o[2], o[3]);
        *(float4*)(dst + 4) = make_float4(o[4], o[5], o[6], o[7]);
    }
}

// ---------------------------------------------------------------------------
// Row softmax over 2048-wide rows, 256 threads, single read + single write.
// ---------------------------------------------------------------------------
__global__ void softmax2048(float* __restrict__ S)
{
    float* p = S + (size_t)blockIdx.x * NN;
    const int tid  = threadIdx.x;
    const int lane = tid & 31;
    const int warp = tid >> 5;
    __shared__ float red[8];

    float v[8];
#pragma unroll
    for (int i = 0; i < 8; i++) v[i] = p[tid + (i << 8)];

    float m = v[0];
#pragma unroll
    for (int i = 1; i < 8; i++) m = fmaxf(m, v[i]);
#pragma unroll
    for (int o = 16; o > 0; o >>= 1) m = fmaxf(m, __shfl_xor_sync(0xffffffffu, m, o));
    if (lane == 0) red[warp] = m;
    __syncthreads();
    if (warp == 0) {
        float t = (lane < 8) ? red[lane] : -1e30f;
#pragma unroll
        for (int o = 16; o > 0; o >>= 1) t = fmaxf(t, __shfl_xor_sync(0xffffffffu, t, o));
        if (lane == 0) red[0] = t;
    }
    __syncthreads();
    m = red[0];
    __syncthreads();

    float s = 0.f;
#pragma unroll
    for (int i = 0; i < 8; i++) { v[i] = __expf(v[i] - m); s += v[i]; }
#pragma unroll
    for (int o = 16; o > 0; o >>= 1) s += __shfl_xor_sync(0xffffffffu, s, o);
    if (lane == 0) red[warp] = s;
    __syncthreads();
    if (warp == 0) {
        float t = (lane < 8) ? red[lane] : 0.f;
#pragma unroll
        for (int o = 16; o > 0; o >>= 1) t += __shfl_xor_sync(0xffffffffu, t, o);
        if (lane == 0) red[0] = t;
    }
    __syncthreads();
    const float inv = 1.0f / red[0];
#pragma unroll
    for (int i = 0; i < 8; i++) p[tid + (i << 8)] = v[i] * inv;
}

// ---------------------------------------------------------------------------
// Launch: x @ {Wq,Wk,Wv}(+b) -> QK^T/16 -> softmax -> PV -> concat @ W0 + b0
// ---------------------------------------------------------------------------
extern "C" void kernel_launch(void* const* d_in, const int* in_sizes, int n_in,
                              void* d_out, int out_size)
{
    const float* x  = (const float*)d_in[0];
    const float* Wq = (const float*)d_in[1];
    const float* bq = (const float*)d_in[2];
    const float* Wk = (const float*)d_in[3];
    const float* bk = (const float*)d_in[4];
    const float* Wv = (const float*)d_in[5];
    const float* bv = (const float*)d_in[6];
    const float* W0 = (const float*)d_in[7];
    const float* b0 = (const float*)d_in[8];
    float* out = (float*)d_out;

    float *Q, *K, *V, *S, *C;
    cudaGetSymbolAddress((void**)&Q, g_Q);
    cudaGetSymbolAddress((void**)&K, g_K);
    cudaGetSymbolAddress((void**)&V, g_V);
    cudaGetSymbolAddress((void**)&S, g_S);
    cudaGetSymbolAddress((void**)&C, g_C);

    const dim3 blk(256);

    // 1) QKV projections: [16384,768] @ [768,256] + bias, batched over 3 heads.
    //    Output layout [h][16384][256] so later batch slices are contiguous.
    {
        const dim3 g(DK / 128, MALL / 128, HH);
        sgemm128<false, true><<<g, blk>>>(
            x, EMB, 0, 0,
            Wq, DK, 0, (long long)EMB * DK,
            bq, 0, DK,
            Q, DK, 0, (long long)MALL * DK,
            EMB, 1.0f, HH);
        sgemm128<false, true><<<g, blk>>>(
            x, EMB, 0, 0,
            Wk, DK, 0, (long long)EMB * DK,
            bk, 0, DK,
            K, DK, 0, (long long)MALL * DK,
            EMB, 1.0f, HH);
        sgemm128<false, true><<<g, blk>>>(
            x, EMB, 0, 0,
            Wv, DV, 0, (long long)EMB * DV,
            bv, 0, DV,
            V, DV, 0, (long long)MALL * DV,
            EMB, 1.0f, HH);
    }

    // 2) Scores: S[z] = (Q[z] @ K[z]^T) / 16, z = h*8+b over 24 batches.
    {
        const dim3 g(NN / 128, NN / 128, HH * BB);
        sgemm128<true, false><<<g, blk>>>(
            Q, DK, 0, (long long)NN * DK,
            K, DK, 0, (long long)NN * DK,
            nullptr, 0, 0,
            S, NN, 0, (long long)NN * NN,
            DK, 0.0625f, HH * BB);
    }

    // 3) Softmax over each of the 24*2048 rows.
    softmax2048<<<HH * BB * NN, 256>>>(S);

    // 4) PV: O[z] = P[z] @ V[z], scattered into concat layout [b*N+n][h*256+d].
    //    z1 = h (stride 256 in C), z2 = b (stride N*EMB in C).
    {
        const dim3 g(DV / 128, NN / 128, HH * BB);
        sgemm128<false, false><<<g, blk>>>(
            S, NN, (long long)BB * NN * NN, (long long)NN * NN,
            V, DV, (long long)BB * NN * DV, (long long)NN * DV,
            nullptr, 0, 0,
            C, HH * DV, DV, (long long)NN * (HH * DV),
            NN, 1.0f, BB);
    }

    // 5) Output projection: [16384,768] @ [768,768] + b0.
    {
        const dim3 g(EMB / 128, MALL / 128, 1);
        sgemm128<false, true><<<g, blk>>>(
            C, HH * DV, 0, 0,
            W0, EMB, 0, 0,
            b0, 0, 0,
            out, EMB, 0, 0,
            HH * DV, 1.0f, 1);
    }
}

// round 5
// speedup vs baseline: 1.7962x; 1.7962x over previous
#include <cuda_runtime.h>
#include <cuda_bf16.h>
#include <cstdint>
#include <cstddef>

// Problem constants
#define EMB   768
#define DK    256
#define DV    256
#define BB    8
#define NN    2048
#define HH    3
#define MALL  (BB*NN)          // 16384

typedef __nv_bfloat16 bf16;
typedef long long ll;

// ---------------------------------------------------------------------------
// Scratch (device globals — allocation is forbidden)
// ---------------------------------------------------------------------------
__device__ float g_V[HH * MALL * DV];              // fp32 V (pre-transpose)
__device__ float g_S[(size_t)HH * BB * NN * NN];   // scores fp32 (402 MB)

__device__ bf16 g_xh[MALL * EMB],  g_xl[MALL * EMB];
__device__ bf16 g_Qh[HH * MALL * DK], g_Ql[HH * MALL * DK];
__device__ bf16 g_Kh[HH * MALL * DK], g_Kl[HH * MALL * DK];
__device__ bf16 g_Vth[HH * MALL * DV], g_Vtl[HH * MALL * DV];        // V^T per (h,b)
__device__ bf16 g_Ph[(size_t)HH * BB * NN * NN], g_Pl[(size_t)HH * BB * NN * NN];
__device__ bf16 g_Ch[MALL * HH * DV], g_Cl[MALL * HH * DV];          // concat hi/lo
__device__ bf16 g_Wqt[HH * DK * EMB], g_Wqtl[HH * DK * EMB];         // W^T [h][256][768]
__device__ bf16 g_Wkt[HH * DK * EMB], g_Wktl[HH * DK * EMB];
__device__ bf16 g_Wvt[HH * DV * EMB], g_Wvtl[HH * DV * EMB];
__device__ bf16 g_W0t[EMB * EMB],     g_W0tl[EMB * EMB];             // W0^T [768][768]

// ---------------------------------------------------------------------------
// PTX helpers (sm_80-compatible only: ldmatrix / mma.sync / cp.async)
// ---------------------------------------------------------------------------
__device__ __forceinline__ uint32_t smem_to_u32(const void* p) {
    uint32_t a;
    asm("{ .reg .u64 t; cvta.to.shared.u64 t, %1; cvt.u32.u64 %0, t; }" : "=r"(a) : "l"(p));
    return a;
}
__device__ __forceinline__ void ldsm4(uint32_t& r0, uint32_t& r1, uint32_t& r2,
                                      uint32_t& r3, uint32_t addr) {
    asm volatile("ldmatrix.sync.aligned.m8n8.x4.shared.b16 {%0,%1,%2,%3}, [%4];"
                 : "=r"(r0), "=r"(r1), "=r"(r2), "=r"(r3) : "r"(addr));
}
__device__ __forceinline__ void mma_bf16(float* d, const uint32_t* a, const uint32_t* b) {
    asm volatile("mma.sync.aligned.m16n8k16.row.col.f32.bf16.bf16.f32 "
                 "{%0,%1,%2,%3}, {%4,%5,%6,%7}, {%8,%9}, {%0,%1,%2,%3};"
                 : "+f"(d[0]), "+f"(d[1]), "+f"(d[2]), "+f"(d[3])
                 : "r"(a[0]), "r"(a[1]), "r"(a[2]), "r"(a[3]), "r"(b[0]), "r"(b[1]));
}

// ---------------------------------------------------------------------------
// Warp-MMA bf16 split GEMM: C[m,n] = alpha * sum_k A[m,k]*B[n,k] (+ bias[n])
//   A: [Mrows,K] bf16 hi/lo K-major.  B: [Nrows,K] bf16 hi/lo K-major.
//   3-pass split accumulation in fp32 registers.
//   Tile 128x128, BK=32, 256 threads, double-buffered cp.async.
//   OMODE 0: fp32 C.  OMODE 1: bf16 hi/lo pair (Coh/Col).
// ---------------------------------------------------------------------------
#define RSB    144                 // smem row stride bytes (64B data + 16B pad... 144=16*9)
#define TILEB  (128 * RSB)         // 18432
#define STAGEB (4 * TILEB)         // 73728: Ah, Al, Bh, Bl
#define GSM    (2 * STAGEB)        // 147456

template<int OMODE>
__global__ __launch_bounds__(256, 1)
void gemm_mma(const bf16* __restrict__ Ah, const bf16* __restrict__ Al,
              ll sA1, ll sA2,
              const bf16* __restrict__ Bh, const bf16* __restrict__ Bl,
              ll sB1, ll sB2,
              const float* __restrict__ bias, ll sb2,
              float* __restrict__ C, bf16* __restrict__ Coh, bf16* __restrict__ Col,
              int ldc, ll sC1, ll sC2,
              int Kdim, float alpha, int Z2)
{
    const int z  = blockIdx.z;
    const int z1 = z / Z2;
    const int z2 = z - z1 * Z2;
    Ah += z1 * sA1 + z2 * sA2;  Al += z1 * sA1 + z2 * sA2;
    Bh += z1 * sB1 + z2 * sB2;  Bl += z1 * sB1 + z2 * sB2;
    if (OMODE == 0) C += z1 * sC1 + z2 * sC2;
    else { Coh += z1 * sC1 + z2 * sC2; Col += z1 * sC1 + z2 * sC2; }
    const float* bptr = bias ? bias + z2 * sb2 : nullptr;

    const int m0 = blockIdx.y * 128;
    const int n0 = blockIdx.x * 128;

    extern __shared__ char smem[];
    const uint32_t sb = smem_to_u32(smem);
    const int tid  = threadIdx.x;
    const int wid  = tid >> 5;
    const int lane = tid & 31;
    const int wm   = wid >> 2;          // 0..1
    const int wn   = wid & 3;           // 0..3

    // load roles: 64 threads per tile (0:Ah 1:Al 2:Bh 3:Bl)
    const int t  = tid >> 6;
    const int u  = tid & 63;
    const int lc = u & 3;               // 16B chunk in row
    const int lr = u >> 2;              // base row, step 16
    const bf16* tsrc = (t == 0) ? Ah : (t == 1) ? Al : (t == 2) ? Bh : Bl;
    const int rowbase = (t < 2) ? m0 : n0;
    const uint32_t dst0 = sb + (uint32_t)(t * TILEB) + (uint32_t)(lr * RSB + lc * 16);
    const int KT = Kdim >> 5;

    auto issue_loads = [&](int kt, int stage) {
        const bf16* src = tsrc + (size_t)(rowbase + lr) * Kdim + (kt << 5) + lc * 8;
        const size_t step = (size_t)16 * Kdim;
        uint32_t d = dst0 + stage * STAGEB;
#pragma unroll
        for (int j = 0; j < 8; j++) {
            asm volatile("cp.async.cg.shared.global [%0], [%1], 16;" :: "r"(d), "l"(src));
            d += 16 * RSB;
            src += step;
        }
        asm volatile("cp.async.commit_group;" ::: "memory");
    };

    float acc[4][4][4];
#pragma unroll
    for (int i = 0; i < 4; i++)
#pragma unroll
        for (int j = 0; j < 4; j++)
#pragma unroll
            for (int q = 0; q < 4; q++) acc[i][j][q] = 0.f;

    issue_loads(0, 0);

    for (int kt = 0; kt < KT; kt++) {
        const int s = kt & 1;
        if (kt + 1 < KT) {
            issue_loads(kt + 1, s ^ 1);
            asm volatile("cp.async.wait_group 1;" ::: "memory");
        } else {
            asm volatile("cp.async.wait_group 0;" ::: "memory");
        }
        __syncthreads();

        const uint32_t base = sb + s * STAGEB;
#pragma unroll
        for (int ks = 0; ks < 2; ks++) {
            const uint32_t colb = ks * 32 + (lane >> 4) * 16;
            const uint32_t arow = (uint32_t)(wm * 64 + (lane & 15)) * RSB + colb;
            const uint32_t brow = (uint32_t)(wn * 32 + (lane & 15)) * RSB + colb;

            uint32_t ah[4][4], al[4][4], bh[4][2], bl[4][2];
#pragma unroll
            for (int mt = 0; mt < 4; mt++) {
                ldsm4(ah[mt][0], ah[mt][1], ah[mt][2], ah[mt][3],
                      base + 0 * TILEB + arow + mt * 16 * RSB);
                ldsm4(al[mt][0], al[mt][1], al[mt][2], al[mt][3],
                      base + 1 * TILEB + arow + mt * 16 * RSB);
            }
#pragma unroll
            for (int nt2 = 0; nt2 < 2; nt2++) {
                uint32_t r0, r1, r2, r3;
                ldsm4(r0, r1, r2, r3, base + 2 * TILEB + brow + nt2 * 16 * RSB);
                bh[nt2 * 2 + 0][0] = r0; bh[nt2 * 2 + 0][1] = r2;
                bh[nt2 * 2 + 1][0] = r1; bh[nt2 * 2 + 1][1] = r3;
                ldsm4(r0, r1, r2, r3, base + 3 * TILEB + brow + nt2 * 16 * RSB);
                bl[nt2 * 2 + 0][0] = r0; bl[nt2 * 2 + 0][1] = r2;
                bl[nt2 * 2 + 1][0] = r1; bl[nt2 * 2 + 1][1] = r3;
            }
#pragma unroll
            for (int mt = 0; mt < 4; mt++)
#pragma unroll
                for (int nt = 0; nt < 4; nt++) {
                    mma_bf16(acc[mt][nt], ah[mt], bh[nt]);
                    mma_bf16(acc[mt][nt], ah[mt], bl[nt]);
                    mma_bf16(acc[mt][nt], al[mt], bh[nt]);
                }
        }
        __syncthreads();
    }

    // ---- epilogue ----
#pragma unroll
    for (int mt = 0; mt < 4; mt++)
#pragma unroll
        for (int nt = 0; nt < 4; nt++) {
            const int row = m0 + wm * 64 + mt * 16 + (lane >> 2);
            const int col = n0 + wn * 32 + nt * 8 + (lane & 3) * 2;
            float b0v = 0.f, b1v = 0.f;
            if (bptr) { b0v = __ldg(bptr + col); b1v = __ldg(bptr + col + 1); }
#pragma unroll
            for (int h = 0; h < 2; h++) {
                const float v0 = acc[mt][nt][2 * h + 0] * alpha + b0v;
                const float v1 = acc[mt][nt][2 * h + 1] * alpha + b1v;
                const size_t off = (size_t)(row + 8 * h) * ldc + col;
                if (OMODE == 0) {
                    *(float2*)(C + off) = make_float2(v0, v1);
                } else {
                    const bf16 h0 = __float2bfloat16(v0);
                    const bf16 h1 = __float2bfloat16(v1);
                    *(__nv_bfloat162*)(Coh + off) = __nv_bfloat162(h0, h1);
                    *(__nv_bfloat162*)(Col + off) = __nv_bfloat162(
                        __float2bfloat16(v0 - __bfloat162float(h0)),
                        __float2bfloat16(v1 - __bfloat162float(h1)));
                }
            }
        }
}

// ---------------------------------------------------------------------------
// fp32 -> (hi, lo) bf16 split, elementwise, 4 elems/thread
// ---------------------------------------------------------------------------
__global__ void split4(const float* __restrict__ in, bf16* __restrict__ oh,
                       bf16* __restrict__ ol, int n4)
{
    const int i = blockIdx.x * blockDim.x + threadIdx.x;
    if (i >= n4) return;
    const float4 v = ((const float4*)in)[i];
    bf16 h0 = __float2bfloat16(v.x), h1 = __float2bfloat16(v.y);
    bf16 h2 = __float2bfloat16(v.z), h3 = __float2bfloat16(v.w);
    bf16 l0 = __float2bfloat16(v.x - __bfloat162float(h0));
    bf16 l1 = __float2bfloat16(v.y - __bfloat162float(h1));
    bf16 l2 = __float2bfloat16(v.z - __bfloat162float(h2));
    bf16 l3 = __float2bfloat16(v.w - __bfloat162float(h3));
    ((__nv_bfloat162*)oh)[2 * i + 0] = __nv_bfloat162(h0, h1);
    ((__nv_bfloat162*)oh)[2 * i + 1] = __nv_bfloat162(h2, h3);
    ((__nv_bfloat162*)ol)[2 * i + 0] = __nv_bfloat162(l0, l1);
    ((__nv_bfloat162*)ol)[2 * i + 1] = __nv_bfloat162(l2, l3);
}

// ---------------------------------------------------------------------------
// Batched transpose + split: in[R][Cc] fp32 -> out_hi/lo [Cc][R] bf16
// ---------------------------------------------------------------------------
__global__ void transpose_split(const float* __restrict__ in, bf16* __restrict__ oh,
                                bf16* __restrict__ ol, int R, int Cc,
                                ll sIn, ll sOut)
{
    __shared__ float tle[32][33];
    const int z = blockIdx.z;
    in += z * sIn;  oh += z * sOut;  ol += z * sOut;
    const int c0 = blockIdx.x * 32, r0 = blockIdx.y * 32;
    const int x = threadIdx.x, y = threadIdx.y;     // block (32, 8)
#pragma unroll
    for (int i = 0; i < 32; i += 8)
        tle[y + i][x] = in[(size_t)(r0 + y + i) * Cc + c0 + x];
    __syncthreads();
#pragma unroll
    for (int i = 0; i < 32; i += 8) {
        const float v = tle[x][y + i];
        const bf16 h = __float2bfloat16(v);
        const size_t o = (size_t)(c0 + y + i) * R + r0 + x;
        oh[o] = h;
        ol[o] = __float2bfloat16(v - __bfloat162float(h));
    }
}

// ---------------------------------------------------------------------------
// Row softmax over 2048-wide rows -> bf16 hi/lo outputs
// ---------------------------------------------------------------------------
__global__ void softmax_split(const float* __restrict__ S, bf16* __restrict__ Ph,
                              bf16* __restrict__ Pl)
{
    const size_t row = (size_t)blockIdx.x * NN;
    const float* p = S + row;
    const int tid  = threadIdx.x;
    const int lane = tid & 31;
    const int warp = tid >> 5;
    __shared__ float red[8];

    float v[8];
#pragma unroll
    for (int i = 0; i < 8; i++) v[i] = p[tid + (i << 8)];

    float m = v[0];
#pragma unroll
    for (int i = 1; i < 8; i++) m = fmaxf(m, v[i]);
#pragma unroll
    for (int o = 16; o > 0; o >>= 1) m = fmaxf(m, __shfl_xor_sync(0xffffffffu, m, o));
    if (lane == 0) red[warp] = m;
    __syncthreads();
    if (warp == 0) {
        float tv = (lane < 8) ? red[lane] : -1e30f;
#pragma unroll
        for (int o = 16; o > 0; o >>= 1) tv = fmaxf(tv, __shfl_xor_sync(0xffffffffu, tv, o));
        if (lane == 0) red[0] = tv;
    }
    __syncthreads();
    m = red[0];
    __syncthreads();

    float s = 0.f;
#pragma unroll
    for (int i = 0; i < 8; i++) { v[i] = __expf(v[i] - m); s += v[i]; }
#pragma unroll
    for (int o = 16; o > 0; o >>= 1) s += __shfl_xor_sync(0xffffffffu, s, o);
    if (lane == 0) red[warp] = s;
    __syncthreads();
    if (warp == 0) {
        float tv = (lane < 8) ? red[lane] : 0.f;
#pragma unroll
        for (int o = 16; o > 0; o >>= 1) tv += __shfl_xor_sync(0xffffffffu, tv, o);
        if (lane == 0) red[0] = tv;
    }
    __syncthreads();
    const float inv = 1.0f / red[0];
#pragma unroll
    for (int i = 0; i < 8; i++) {
        const float w = v[i] * inv;
        const bf16 h = __float2bfloat16(w);
        const size_t o = row + tid + (i << 8);
        Ph[o] = h;
        Pl[o] = __float2bfloat16(w - __bfloat162float(h));
    }
}

// ---------------------------------------------------------------------------
// Launch
// ---------------------------------------------------------------------------
extern "C" void kernel_launch(void* const* d_in, const int* in_sizes, int n_in,
                              void* d_out, int out_size)
{
    const float* x  = (const float*)d_in[0];
    const float* Wq = (const float*)d_in[1];
    const float* bq = (const float*)d_in[2];
    const float* Wk = (const float*)d_in[3];
    const float* bk = (const float*)d_in[4];
    const float* Wv = (const float*)d_in[5];
    const float* bv = (const float*)d_in[6];
    const float* W0 = (const float*)d_in[7];
    const float* b0 = (const float*)d_in[8];
    float* out = (float*)d_out;

    float *V, *S;
    bf16 *xh, *xl, *Qh, *Ql, *Kh, *Kl, *Vth, *Vtl, *Ph, *Pl, *Ch, *Cl;
    bf16 *Wqt, *Wqtl, *Wkt, *Wktl, *Wvt, *Wvtl, *W0t, *W0tl;
    cudaGetSymbolAddress((void**)&V, g_V);    cudaGetSymbolAddress((void**)&S, g_S);
    cudaGetSymbolAddress((void**)&xh, g_xh);  cudaGetSymbolAddress((void**)&xl, g_xl);
    cudaGetSymbolAddress((void**)&Qh, g_Qh);  cudaGetSymbolAddress((void**)&Ql, g_Ql);
    cudaGetSymbolAddress((void**)&Kh, g_Kh);  cudaGetSymbolAddress((void**)&Kl, g_Kl);
    cudaGetSymbolAddress((void**)&Vth, g_Vth);cudaGetSymbolAddress((void**)&Vtl, g_Vtl);
    cudaGetSymbolAddress((void**)&Ph, g_Ph);  cudaGetSymbolAddress((void**)&Pl, g_Pl);
    cudaGetSymbolAddress((void**)&Ch, g_Ch);  cudaGetSymbolAddress((void**)&Cl, g_Cl);
    cudaGetSymbolAddress((void**)&Wqt, g_Wqt);   cudaGetSymbolAddress((void**)&Wqtl, g_Wqtl);
    cudaGetSymbolAddress((void**)&Wkt, g_Wkt);   cudaGetSymbolAddress((void**)&Wktl, g_Wktl);
    cudaGetSymbolAddress((void**)&Wvt, g_Wvt);   cudaGetSymbolAddress((void**)&Wvtl, g_Wvtl);
    cudaGetSymbolAddress((void**)&W0t, g_W0t);   cudaGetSymbolAddress((void**)&W0tl, g_W0tl);

    cudaFuncSetAttribute(gemm_mma<0>, cudaFuncAttributeMaxDynamicSharedMemorySize, GSM);
    cudaFuncSetAttribute(gemm_mma<1>, cudaFuncAttributeMaxDynamicSharedMemorySize, GSM);

    const dim3 tb(32, 8);

    // --- operand prep ---
    split4<<<(MALL * EMB / 4 + 255) / 256, 256>>>(x, xh, xl, MALL * EMB / 4);
    transpose_split<<<dim3(8, 24, 3), tb>>>(Wq, Wqt, Wqtl, EMB, DK,
                                            (ll)EMB * DK, (ll)EMB * DK);
    transpose_split<<<dim3(8, 24, 3), tb>>>(Wk, Wkt, Wktl, EMB, DK,
                                            (ll)EMB * DK, (ll)EMB * DK);
    transpose_split<<<dim3(8, 24, 3), tb>>>(Wv, Wvt, Wvtl, EMB, DV,
                                            (ll)EMB * DV, (ll)EMB * DV);
    transpose_split<<<dim3(24, 24, 1), tb>>>(W0, W0t, W0tl, EMB, EMB, 0, 0);

    // --- QKV projections: [16384,768] x [256,768]^T, batched over 3 heads ---
    {
        const dim3 g(DK / 128, MALL / 128, HH);
        // Q, K write bf16 hi/lo directly (consumed only by scores GEMM)
        gemm_mma<1><<<g, 256, GSM>>>(xh, xl, 0, 0,
                                     Wqt, Wqtl, 0, (ll)DK * EMB,
                                     bq, DK,
                                     nullptr, Qh, Ql, DK, 0, (ll)MALL * DK,
                                     EMB, 1.0f, HH);
        gemm_mma<1><<<g, 256, GSM>>>(xh, xl, 0, 0,
                                     Wkt, Wktl, 0, (ll)DK * EMB,
                                     bk, DK,
                                     nullptr, Kh, Kl, DK, 0, (ll)MALL * DK,
                                     EMB, 1.0f, HH);
        // V stays fp32 (needs a transpose pass)
        gemm_mma<0><<<g, 256, GSM>>>(xh, xl, 0, 0,
                                     Wvt, Wvtl, 0, (ll)DV * EMB,
                                     bv, DV,
                                     V, nullptr, nullptr, DV, 0, (ll)MALL * DV,
                                     EMB, 1.0f, HH);
    }

    // --- transpose+split V: [NN,DV] -> [DV,NN] per (h,b) ---
    transpose_split<<<dim3(DV / 32, NN / 32, HH * BB), tb>>>(
        V, Vth, Vtl, NN, DV, (ll)NN * DV, (ll)NN * DV);

    // --- scores: S = (Q K^T) / 16 over 24 (h,b) batches ---
    gemm_mma<0><<<dim3(NN / 128, NN / 128, HH * BB), 256, GSM>>>(
        Qh, Ql, (ll)MALL * DK, (ll)NN * DK,
        Kh, Kl, (ll)MALL * DK, (ll)NN * DK,
        nullptr, 0,
        S, nullptr, nullptr, NN, (ll)BB * NN * NN, (ll)NN * NN,
        DK, 0.0625f, BB);

    // --- softmax -> P hi/lo ---
    softmax_split<<<HH * BB * NN, 256>>>(S, Ph, Pl);

    // --- PV: O = P V into concat layout [b*N+n][h*256+d], bf16 hi/lo out ---
    gemm_mma<1><<<dim3(DV / 128, NN / 128, HH * BB), 256, GSM>>>(
        Ph, Pl, (ll)BB * NN * NN, (ll)NN * NN,
        Vth, Vtl, (ll)BB * DV * NN, (ll)DV * NN,
        nullptr, 0,
        nullptr, Ch, Cl, HH * DV, DV, (ll)NN * (HH * DV),
        NN, 1.0f, BB);

    // --- output projection: [16384,768] x [768,768]^T + b0 ---
    gemm_mma<0><<<dim3(EMB / 128, MALL / 128, 1), 256, GSM>>>(
        Ch, Cl, 0, 0,
        W0t, W0tl, 0, 0,
        b0, 0,
        out, nullptr, nullptr, EMB, 0, 0,
        HH * DV, 1.0f, 1);
}

// round 7
// speedup vs baseline: 2.0688x; 1.1518x over previous
#include <cuda_runtime.h>
#include <cuda_bf16.h>
#include <cstdint>
#include <cstddef>

// Problem constants
#define EMB   768
#define DK    256
#define DV    256
#define BB    8
#define NN    2048
#define HH    3
#define MALL  (BB*NN)          // 16384

typedef __nv_bfloat16 bf16;
typedef long long ll;

// ---------------------------------------------------------------------------
// Scratch (device globals — allocation is forbidden)
// ---------------------------------------------------------------------------
__device__ float g_V[HH * MALL * DV];              // fp32 V (pre-transpose)
__device__ float g_S[(size_t)HH * BB * NN * NN];   // scores fp32 (402 MB)

__device__ bf16 g_xh[MALL * EMB],  g_xl[MALL * EMB];
__device__ bf16 g_Qh[HH * MALL * DK], g_Ql[HH * MALL * DK];
__device__ bf16 g_Kh[HH * MALL * DK], g_Kl[HH * MALL * DK];
__device__ bf16 g_Vth[HH * MALL * DV], g_Vtl[HH * MALL * DV];        // V^T per (h,b)
__device__ bf16 g_Ph[(size_t)HH * BB * NN * NN], g_Pl[(size_t)HH * BB * NN * NN];
__device__ bf16 g_Ch[MALL * HH * DV], g_Cl[MALL * HH * DV];          // concat hi/lo
__device__ bf16 g_Wqt[HH * DK * EMB], g_Wqtl[HH * DK * EMB];         // W^T [h][256][768]
__device__ bf16 g_Wkt[HH * DK * EMB], g_Wktl[HH * DK * EMB];
__device__ bf16 g_Wvt[HH * DV * EMB], g_Wvtl[HH * DV * EMB];
__device__ bf16 g_W0t[EMB * EMB],     g_W0tl[EMB * EMB];             // W0^T [768][768]

// ---------------------------------------------------------------------------
// PTX helpers (sm_80-compatible only: ldmatrix / mma.sync / cp.async)
// ---------------------------------------------------------------------------
__device__ __forceinline__ uint32_t smem_to_u32(const void* p) {
    uint32_t a;
    asm("{ .reg .u64 t; cvta.to.shared.u64 t, %1; cvt.u32.u64 %0, t; }" : "=r"(a) : "l"(p));
    return a;
}
__device__ __forceinline__ void ldsm4(uint32_t& r0, uint32_t& r1, uint32_t& r2,
                                      uint32_t& r3, uint32_t addr) {
    asm volatile("ldmatrix.sync.aligned.m8n8.x4.shared.b16 {%0,%1,%2,%3}, [%4];"
                 : "=r"(r0), "=r"(r1), "=r"(r2), "=r"(r3) : "r"(addr));
}
__device__ __forceinline__ void mma_bf16(float* d, const uint32_t* a, const uint32_t* b) {
    asm volatile("mma.sync.aligned.m16n8k16.row.col.f32.bf16.bf16.f32 "
                 "{%0,%1,%2,%3}, {%4,%5,%6,%7}, {%8,%9}, {%0,%1,%2,%3};"
                 : "+f"(d[0]), "+f"(d[1]), "+f"(d[2]), "+f"(d[3])
                 : "r"(a[0]), "r"(a[1]), "r"(a[2]), "r"(a[3]), "r"(b[0]), "r"(b[1]));
}

// ---------------------------------------------------------------------------
// Warp-MMA bf16 split GEMM: C[m,n] = alpha * sum_k A[m,k]*B[n,k] (+ bias[n])
//   A: [Mrows,K] bf16 hi/lo K-major.  B: [Nrows,K] bf16 hi/lo K-major.
//   3-pass split accumulation (AhBh + AhBl + AlBh) in fp32 registers.
//   Tile 128x128, BK=32, 256 threads, double-buffered cp.async, 2 CTAs/SM.
//   OMODE 0: fp32 C.  OMODE 1: bf16 hi/lo pair (Coh/Col).
// ---------------------------------------------------------------------------
#define RSB    80                  // 64B data + 16B pad; conflict-free ldmatrix
#define TILEB  (128 * RSB)         // 10240
#define STAGEB (4 * TILEB)         // 40960: Ah, Al, Bh, Bl
#define GSM    (2 * STAGEB)        // 81920 -> 2 CTAs/SM

template<int OMODE>
__global__ __launch_bounds__(256, 2)
void gemm_mma(const bf16* __restrict__ Ah, const bf16* __restrict__ Al,
              ll sA1, ll sA2,
              const bf16* __restrict__ Bh, const bf16* __restrict__ Bl,
              ll sB1, ll sB2,
              const float* __restrict__ bias, ll sb2,
              float* __restrict__ C, bf16* __restrict__ Coh, bf16* __restrict__ Col,
              int ldc, ll sC1, ll sC2,
              int Kdim, float alpha, int Z2)
{
    const int z  = blockIdx.z;
    const int z1 = z / Z2;
    const int z2 = z - z1 * Z2;
    Ah += z1 * sA1 + z2 * sA2;  Al += z1 * sA1 + z2 * sA2;
    Bh += z1 * sB1 + z2 * sB2;  Bl += z1 * sB1 + z2 * sB2;
    if (OMODE == 0) C += z1 * sC1 + z2 * sC2;
    else { Coh += z1 * sC1 + z2 * sC2; Col += z1 * sC1 + z2 * sC2; }
    const float* bptr = bias ? bias + z2 * sb2 : nullptr;

    const int m0 = blockIdx.y * 128;
    const int n0 = blockIdx.x * 128;

    extern __shared__ char smem[];
    const uint32_t sb = smem_to_u32(smem);
    const int tid  = threadIdx.x;
    const int wid  = tid >> 5;
    const int lane = tid & 31;
    const int wm   = wid >> 2;          // 0..1
    const int wn   = wid & 3;           // 0..3

    // load roles: 64 threads per tile (0:Ah 1:Al 2:Bh 3:Bl)
    const int t  = tid >> 6;
    const int u  = tid & 63;
    const int lc = u & 3;               // 16B chunk in row
    const int lr = u >> 2;              // base row, step 16
    const bf16* tsrc = (t == 0) ? Ah : (t == 1) ? Al : (t == 2) ? Bh : Bl;
    const int rowbase = (t < 2) ? m0 : n0;
    const uint32_t dst0 = sb + (uint32_t)(t * TILEB) + (uint32_t)(lr * RSB + lc * 16);
    const int KT = Kdim >> 5;

    auto issue_loads = [&](int kt, int stage) {
        const bf16* src = tsrc + (size_t)(rowbase + lr) * Kdim + (kt << 5) + lc * 8;
        const size_t step = (size_t)16 * Kdim;
        uint32_t d = dst0 + stage * STAGEB;
#pragma unroll
        for (int j = 0; j < 8; j++) {
            asm volatile("cp.async.cg.shared.global [%0], [%1], 16;" :: "r"(d), "l"(src));
            d += 16 * RSB;
            src += step;
        }
        asm volatile("cp.async.commit_group;" ::: "memory");
    };

    float acc[4][4][4];
#pragma unroll
    for (int i = 0; i < 4; i++)
#pragma unroll
        for (int j = 0; j < 4; j++)
#pragma unroll
            for (int q = 0; q < 4; q++) acc[i][j][q] = 0.f;

    issue_loads(0, 0);

    for (int kt = 0; kt < KT; kt++) {
        const int s = kt & 1;
        if (kt + 1 < KT) {
            issue_loads(kt + 1, s ^ 1);
            asm volatile("cp.async.wait_group 1;" ::: "memory");
        } else {
            asm volatile("cp.async.wait_group 0;" ::: "memory");
        }
        __syncthreads();

        const uint32_t base = sb + s * STAGEB;
#pragma unroll
        for (int ks = 0; ks < 2; ks++) {
            const uint32_t colb = ks * 32 + (lane >> 4) * 16;
            const uint32_t arow = base + (uint32_t)(wm * 64 + (lane & 15)) * RSB + colb;
            const uint32_t brow = base + (uint32_t)(wn * 32 + (lane & 15)) * RSB + colb;

            // B fragments for this ks (16 regs), loaded once
            uint32_t bh[4][2], bl[4][2];
#pragma unroll
            for (int nt2 = 0; nt2 < 2; nt2++) {
                uint32_t r0, r1, r2, r3;
                ldsm4(r0, r1, r2, r3, 2 * TILEB + brow + nt2 * 16 * RSB);
                bh[nt2 * 2 + 0][0] = r0; bh[nt2 * 2 + 0][1] = r2;
                bh[nt2 * 2 + 1][0] = r1; bh[nt2 * 2 + 1][1] = r3;
                ldsm4(r0, r1, r2, r3, 3 * TILEB + brow + nt2 * 16 * RSB);
                bl[nt2 * 2 + 0][0] = r0; bl[nt2 * 2 + 0][1] = r2;
                bl[nt2 * 2 + 1][0] = r1; bl[nt2 * 2 + 1][1] = r3;
            }
            // A fragments per mt (8 regs live), 12 MMAs each
#pragma unroll
            for (int mt = 0; mt < 4; mt++) {
                uint32_t ah[4], al[4];
                ldsm4(ah[0], ah[1], ah[2], ah[3], 0 * TILEB + arow + mt * 16 * RSB);
                ldsm4(al[0], al[1], al[2], al[3], 1 * TILEB + arow + mt * 16 * RSB);
#pragma unroll
                for (int nt = 0; nt < 4; nt++) {
                    mma_bf16(acc[mt][nt], ah, bh[nt]);
                    mma_bf16(acc[mt][nt], ah, bl[nt]);
                    mma_bf16(acc[mt][nt], al, bh[nt]);
                }
            }
        }
        __syncthreads();
    }

    // ---- epilogue ----
#pragma unroll
    for (int mt = 0; mt < 4; mt++)
#pragma unroll
        for (int nt = 0; nt < 4; nt++) {
            const int row = m0 + wm * 64 + mt * 16 + (lane >> 2);
            const int col = n0 + wn * 32 + nt * 8 + (lane & 3) * 2;
            float b0v = 0.f, b1v = 0.f;
            if (bptr) { b0v = __ldg(bptr + col); b1v = __ldg(bptr + col + 1); }
#pragma unroll
            for (int h = 0; h < 2; h++) {
                const float v0 = acc[mt][nt][2 * h + 0] * alpha + b0v;
                const float v1 = acc[mt][nt][2 * h + 1] * alpha + b1v;
                const size_t off = (size_t)(row + 8 * h) * ldc + col;
                if (OMODE == 0) {
                    *(float2*)(C + off) = make_float2(v0, v1);
                } else {
                    const bf16 h0 = __float2bfloat16(v0);
                    const bf16 h1 = __float2bfloat16(v1);
                    *(__nv_bfloat162*)(Coh + off) = __nv_bfloat162(h0, h1);
                    *(__nv_bfloat162*)(Col + off) = __nv_bfloat162(
                        __float2bfloat16(v0 - __bfloat162float(h0)),
                        __float2bfloat16(v1 - __bfloat162float(h1)));
                }
            }
        }
}

// ---------------------------------------------------------------------------
// fp32 -> (hi, lo) bf16 split, elementwise, 4 elems/thread
// ---------------------------------------------------------------------------
__global__ void split4(const float* __restrict__ in, bf16* __restrict__ oh,
                       bf16* __restrict__ ol, int n4)
{
    const int i = blockIdx.x * blockDim.x + threadIdx.x;
    if (i >= n4) return;
    const float4 v = ((const float4*)in)[i];
    bf16 h0 = __float2bfloat16(v.x), h1 = __float2bfloat16(v.y);
    bf16 h2 = __float2bfloat16(v.z), h3 = __float2bfloat16(v.w);
    bf16 l0 = __float2bfloat16(v.x - __bfloat162float(h0));
    bf16 l1 = __float2bfloat16(v.y - __bfloat162float(h1));
    bf16 l2 = __float2bfloat16(v.z - __bfloat162float(h2));
    bf16 l3 = __float2bfloat16(v.w - __bfloat162float(h3));
    ((__nv_bfloat162*)oh)[2 * i + 0] = __nv_bfloat162(h0, h1);
    ((__nv_bfloat162*)oh)[2 * i + 1] = __nv_bfloat162(h2, h3);
    ((__nv_bfloat162*)ol)[2 * i + 0] = __nv_bfloat162(l0, l1);
    ((__nv_bfloat162*)ol)[2 * i + 1] = __nv_bfloat162(l2, l3);
}

// ---------------------------------------------------------------------------
// Batched transpose + split: in[R][Cc] fp32 -> out_hi/lo [Cc][R] bf16
// ---------------------------------------------------------------------------
__global__ void transpose_split(const float* __restrict__ in, bf16* __restrict__ oh,
                                bf16* __restrict__ ol, int R, int Cc,
                                ll sIn, ll sOut)
{
    __shared__ float tle[32][33];
    const int z = blockIdx.z;
    in += z * sIn;  oh += z * sOut;  ol += z * sOut;
    const int c0 = blockIdx.x * 32, r0 = blockIdx.y * 32;
    const int x = threadIdx.x, y = threadIdx.y;     // block (32, 8)
#pragma unroll
    for (int i = 0; i < 32; i += 8)
        tle[y + i][x] = in[(size_t)(r0 + y + i) * Cc + c0 + x];
    __syncthreads();
#pragma unroll
    for (int i = 0; i < 32; i += 8) {
        const float v = tle[x][y + i];
        const bf16 h = __float2bfloat16(v);
        const size_t o = (size_t)(c0 + y + i) * R + r0 + x;
        oh[o] = h;
        ol[o] = __float2bfloat16(v - __bfloat162float(h));
    }
}

// ---------------------------------------------------------------------------
// Row softmax over 2048-wide rows -> bf16 hi/lo outputs
// ---------------------------------------------------------------------------
__global__ void softmax_split(const float* __restrict__ S, bf16* __restrict__ Ph,
                              bf16* __restrict__ Pl)
{
    const size_t row = (size_t)blockIdx.x * NN;
    const float* p = S + row;
    const int tid  = threadIdx.x;
    const int lane = tid & 31;
    const int warp = tid >> 5;
    __shared__ float red[8];

    float v[8];
#pragma unroll
    for (int i = 0; i < 8; i++) v[i] = p[tid + (i << 8)];

    float m = v[0];
#pragma unroll
    for (int i = 1; i < 8; i++) m = fmaxf(m, v[i]);
#pragma unroll
    for (int o = 16; o > 0; o >>= 1) m = fmaxf(m, __shfl_xor_sync(0xffffffffu, m, o));
    if (lane == 0) red[warp] = m;
    __syncthreads();
    if (warp == 0) {
        float tv = (lane < 8) ? red[lane] : -1e30f;
#pragma unroll
        for (int o = 16; o > 0; o >>= 1) tv = fmaxf(tv, __shfl_xor_sync(0xffffffffu, tv, o));
        if (lane == 0) red[0] = tv;
    }
    __syncthreads();
    m = red[0];
    __syncthreads();

    float s = 0.f;
#pragma unroll
    for (int i = 0; i < 8; i++) { v[i] = __expf(v[i] - m); s += v[i]; }
#pragma unroll
    for (int o = 16; o > 0; o >>= 1) s += __shfl_xor_sync(0xffffffffu, s, o);
    if (lane == 0) red[warp] = s;
    __syncthreads();
    if (warp == 0) {
        float tv = (lane < 8) ? red[lane] : 0.f;
#pragma unroll
        for (int o = 16; o > 0; o >>= 1) tv += __shfl_xor_sync(0xffffffffu, tv, o);
        if (lane == 0) red[0] = tv;
    }
    __syncthreads();
    const float inv = 1.0f / red[0];
#pragma unroll
    for (int i = 0; i < 8; i++) {
        const float w = v[i] * inv;
        const bf16 h = __float2bfloat16(w);
        const size_t o = row + tid + (i << 8);
        Ph[o] = h;
        Pl[o] = __float2bfloat16(w - __bfloat162float(h));
    }
}

// ---------------------------------------------------------------------------
// Launch
// ---------------------------------------------------------------------------
extern "C" void kernel_launch(void* const* d_in, const int* in_sizes, int n_in,
                              void* d_out, int out_size)
{
    const float* x  = (const float*)d_in[0];
    const float* Wq = (const float*)d_in[1];
    const float* bq = (const float*)d_in[2];
    const float* Wk = (const float*)d_in[3];
    const float* bk = (const float*)d_in[4];
    const float* Wv = (const float*)d_in[5];
    const float* bv = (const float*)d_in[6];
    const float* W0 = (const float*)d_in[7];
    const float* b0 = (const float*)d_in[8];
    float* out = (float*)d_out;

    float *V, *S;
    bf16 *xh, *xl, *Qh, *Ql, *Kh, *Kl, *Vth, *Vtl, *Ph, *Pl, *Ch, *Cl;
    bf16 *Wqt, *Wqtl, *Wkt, *Wktl, *Wvt, *Wvtl, *W0t, *W0tl;
    cudaGetSymbolAddress((void**)&V, g_V);    cudaGetSymbolAddress((void**)&S, g_S);
    cudaGetSymbolAddress((void**)&xh, g_xh);  cudaGetSymbolAddress((void**)&xl, g_xl);
    cudaGetSymbolAddress((void**)&Qh, g_Qh);  cudaGetSymbolAddress((void**)&Ql, g_Ql);
    cudaGetSymbolAddress((void**)&Kh, g_Kh);  cudaGetSymbolAddress((void**)&Kl, g_Kl);
    cudaGetSymbolAddress((void**)&Vth, g_Vth);cudaGetSymbolAddress((void**)&Vtl, g_Vtl);
    cudaGetSymbolAddress((void**)&Ph, g_Ph);  cudaGetSymbolAddress((void**)&Pl, g_Pl);
    cudaGetSymbolAddress((void**)&Ch, g_Ch);  cudaGetSymbolAddress((void**)&Cl, g_Cl);
    cudaGetSymbolAddress((void**)&Wqt, g_Wqt);   cudaGetSymbolAddress((void**)&Wqtl, g_Wqtl);
    cudaGetSymbolAddress((void**)&Wkt, g_Wkt);   cudaGetSymbolAddress((void**)&Wktl, g_Wktl);
    cudaGetSymbolAddress((void**)&Wvt, g_Wvt);   cudaGetSymbolAddress((void**)&Wvtl, g_Wvtl);
    cudaGetSymbolAddress((void**)&W0t, g_W0t);   cudaGetSymbolAddress((void**)&W0tl, g_W0tl);

    cudaFuncSetAttribute(gemm_mma<0>, cudaFuncAttributeMaxDynamicSharedMemorySize, GSM);
    cudaFuncSetAttribute(gemm_mma<1>, cudaFuncAttributeMaxDynamicSharedMemorySize, GSM);

    const dim3 tb(32, 8);

    // --- operand prep ---
    split4<<<(MALL * EMB / 4 + 255) / 256, 256>>>(x, xh, xl, MALL * EMB / 4);
    transpose_split<<<dim3(8, 24, 3), tb>>>(Wq, Wqt, Wqtl, EMB, DK,
                                            (ll)EMB * DK, (ll)EMB * DK);
    transpose_split<<<dim3(8, 24, 3), tb>>>(Wk, Wkt, Wktl, EMB, DK,
                                            (ll)EMB * DK, (ll)EMB * DK);
    transpose_split<<<dim3(8, 24, 3), tb>>>(Wv, Wvt, Wvtl, EMB, DV,
                                            (ll)EMB * DV, (ll)EMB * DV);
    transpose_split<<<dim3(24, 24, 1), tb>>>(W0, W0t, W0tl, EMB, EMB, 0, 0);

    // --- QKV projections: [16384,768] x [256,768]^T, batched over 3 heads ---
    {
        const dim3 g(DK / 128, MALL / 128, HH);
        // Q, K write bf16 hi/lo directly (consumed only by scores GEMM)
        gemm_mma<1><<<g, 256, GSM>>>(xh, xl, 0, 0,
                                     Wqt, Wqtl, 0, (ll)DK * EMB,
                                     bq, DK,
                                     nullptr, Qh, Ql, DK, 0, (ll)MALL * DK,
                                     EMB, 1.0f, HH);
        gemm_mma<1><<<g, 256, GSM>>>(xh, xl, 0, 0,
                                     Wkt, Wktl, 0, (ll)DK * EMB,
                                     bk, DK,
                                     nullptr, Kh, Kl, DK, 0, (ll)MALL * DK,
                                     EMB, 1.0f, HH);
        // V stays fp32 (needs a transpose pass)
        gemm_mma<0><<<g, 256, GSM>>>(xh, xl, 0, 0,
                                     Wvt, Wvtl, 0, (ll)DV * EMB,
                                     bv, DV,
                                     V, nullptr, nullptr, DV, 0, (ll)MALL * DV,
                                     EMB, 1.0f, HH);
    }

    // --- transpose+split V: [NN,DV] -> [DV,NN] per (h,b) ---
    transpose_split<<<dim3(DV / 32, NN / 32, HH * BB), tb>>>(
        V, Vth, Vtl, NN, DV, (ll)NN * DV, (ll)NN * DV);

    // --- scores: S = (Q K^T) / 16 over 24 (h,b) batches ---
    gemm_mma<0><<<dim3(NN / 128, NN / 128, HH * BB), 256, GSM>>>(
        Qh, Ql, (ll)MALL * DK, (ll)NN * DK,
        Kh, Kl, (ll)MALL * DK, (ll)NN * DK,
        nullptr, 0,
        S, nullptr, nullptr, NN, (ll)BB * NN * NN, (ll)NN * NN,
        DK, 0.0625f, BB);

    // --- softmax -> P hi/lo ---
    softmax_split<<<HH * BB * NN, 256>>>(S, Ph, Pl);

    // --- PV: O = P V into concat layout [b*N+n][h*256+d], bf16 hi/lo out ---
    gemm_mma<1><<<dim3(DV / 128, NN / 128, HH * BB), 256, GSM>>>(
        Ph, Pl, (ll)BB * NN * NN, (ll)NN * NN,
        Vth, Vtl, (ll)BB * DV * NN, (ll)DV * NN,
        nullptr, 0,
        nullptr, Ch, Cl, HH * DV, DV, (ll)NN * (HH * DV),
        NN, 1.0f, BB);

    // --- output projection: [16384,768] x [768,768]^T + b0 ---
    gemm_mma<0><<<dim3(EMB / 128, MALL / 128, 1), 256, GSM>>>(
        Ch, Cl, 0, 0,
        W0t, W0tl, 0, 0,
        b0, 0,
        out, nullptr, nullptr, EMB, 0, 0,
        HH * DV, 1.0f, 1);
}